// round 6
// baseline (speedup 1.0000x reference)
#include <cuda_runtime.h>

#define NT   262144
#define KC   512
#define DD   64
#define TPB  256
#define TOKENS_PER_BLOCK (TPB * 2)
#define GRID (NT / TOKENS_PER_BLOCK)
#define SMEM_BYTES ((KC * DD + KC) * 4)

typedef unsigned long long u64;

__device__ double g_loss_acc;          // zero-init; reset by last block each run
__device__ unsigned int g_done_ctr;    // zero-init; reset by last block each run

// Packed 2-wide fp32 FMA (Blackwell FFMA2)
__device__ __forceinline__ u64 ffma2(u64 a, u64 b, u64 c) {
    u64 d;
    asm("fma.rn.f32x2 %0, %1, %2, %3;" : "=l"(d) : "l"(a), "l"(b), "l"(c));
    return d;
}

__device__ __forceinline__ float2 unpack2(u64 v) {
    float2 r;
    asm("mov.b64 {%0, %1}, %2;" : "=f"(r.x), "=f"(r.y) : "l"(v));
    return r;
}

// Branchless top-3 ascending insert
__device__ __forceinline__ void top3(float s, int kk,
                                     float& v0, float& v1, float& v2,
                                     int& i0, int& i1, int& i2) {
    bool lt0 = s < v0, lt1 = s < v1, lt2 = s < v2;
    float nv2 = lt2 ? (lt1 ? v1 : s) : v2;
    int   ni2 = lt2 ? (lt1 ? i1 : kk) : i2;
    float nv1 = lt1 ? (lt0 ? v0 : s) : v1;
    int   ni1 = lt1 ? (lt0 ? i0 : kk) : i1;
    float nv0 = lt0 ? s : v0;
    int   ni0 = lt0 ? kk : i0;
    v0 = nv0; v1 = nv1; v2 = nv2; i0 = ni0; i1 = ni1; i2 = ni2;
}

// Exact rescore (reference rounding: fl(fl(S+c2)-fl(2*dot)), sequential fp32
// FMA, first-index tie-break) + STE epilogue for one token. Returns loss part.
__device__ __forceinline__ float finish_token(const u64* zq, int tok,
                                              const float* s_cb,
                                              const float* s_c2,
                                              float* out,
                                              int c0, int c1, int c2i) {
    float S = 0.0f;
#pragma unroll
    for (int i = 0; i < DD / 2; ++i) {
        float2 p = unpack2(zq[i]);
        S = __fmaf_rn(p.x, p.x, S);
        S = __fmaf_rn(p.y, p.y, S);
    }
    const float* ra = s_cb + c0 * DD;
    const float* rb = s_cb + c1 * DD;
    const float* rc = s_cb + c2i * DD;
    float da = 0.0f, db = 0.0f, dc = 0.0f;
#pragma unroll
    for (int i = 0; i < DD / 2; ++i) {
        float2 p = unpack2(zq[i]);
        da = __fmaf_rn(ra[2 * i], p.x, da); da = __fmaf_rn(ra[2 * i + 1], p.y, da);
        db = __fmaf_rn(rb[2 * i], p.x, db); db = __fmaf_rn(rb[2 * i + 1], p.y, db);
        dc = __fmaf_rn(rc[2 * i], p.x, dc); dc = __fmaf_rn(rc[2 * i + 1], p.y, dc);
    }
    float e0 = __fsub_rn(__fadd_rn(S, s_c2[c0]),  __fmul_rn(2.0f, da));
    float e1 = __fsub_rn(__fadd_rn(S, s_c2[c1]),  __fmul_rn(2.0f, db));
    float e2 = __fsub_rn(__fadd_rn(S, s_c2[c2i]), __fmul_rn(2.0f, dc));

    int   bestk = c0;
    float bests = e0;
    if (e1 < bests || (e1 == bests && c1 < bestk))  { bests = e1; bestk = c1; }
    if (e2 < bests || (e2 == bests && c2i < bestk)) { bests = e2; bestk = c2i; }

    const float4* q = (const float4*)(s_cb + bestk * DD);
    float4* op = (float4*)(out + (size_t)tok * DD);
    float lacc = 0.0f;
#pragma unroll
    for (int i = 0; i < DD / 4; ++i) {
        float4 c = q[i];
        float2 plo = unpack2(zq[2 * i]);
        float2 phi = unpack2(zq[2 * i + 1]);
        float4 o; float dx;
        dx = __fsub_rn(c.x, plo.x); o.x = __fadd_rn(plo.x, dx); lacc = __fmaf_rn(dx, dx, lacc);
        dx = __fsub_rn(c.y, plo.y); o.y = __fadd_rn(plo.y, dx); lacc = __fmaf_rn(dx, dx, lacc);
        dx = __fsub_rn(c.z, phi.x); o.z = __fadd_rn(phi.x, dx); lacc = __fmaf_rn(dx, dx, lacc);
        dx = __fsub_rn(c.w, phi.y); o.w = __fadd_rn(phi.y, dx); lacc = __fmaf_rn(dx, dx, lacc);
        op[i] = o;
    }
    return lacc;
}

__global__ void __launch_bounds__(TPB) vq_fused(const float* __restrict__ z,
                                                const float* __restrict__ cb,
                                                float* __restrict__ out,
                                                int loss_idx) {
    extern __shared__ float sm[];
    float* s_cb = sm;             // [KC*DD] codebook fp32
    float* s_c2 = sm + KC * DD;   // [KC] squared norms
    __shared__ double s_red[TPB / 32];

    for (int i = threadIdx.x; i < KC * DD / 4; i += TPB)
        ((float4*)s_cb)[i] = ((const float4*)cb)[i];
    __syncthreads();

    for (int k = threadIdx.x; k < KC; k += TPB) {
        const float* row = s_cb + k * DD;
        float s = 0.0f;
#pragma unroll
        for (int d = 0; d < DD; ++d) s = __fmaf_rn(row[d], row[d], s);
        s_c2[k] = s;
    }
    __syncthreads();

    const int tok0 = blockIdx.x * TOKENS_PER_BLOCK + threadIdx.x;
    const int tok1 = tok0 + TPB;

    u64 zq0[DD / 2], zq1[DD / 2];
    {
        const ulonglong2* zp0 = (const ulonglong2*)(z + (size_t)tok0 * DD);
        const ulonglong2* zp1 = (const ulonglong2*)(z + (size_t)tok1 * DD);
#pragma unroll
        for (int i = 0; i < DD / 4; ++i) {
            ulonglong2 a = zp0[i];
            zq0[2 * i] = a.x; zq0[2 * i + 1] = a.y;
            ulonglong2 b = zp1[i];
            zq1[2 * i] = b.x; zq1[2 * i + 1] = b.y;
        }
    }

    // ---- Filter: approx score fl(c2_k - fl(2*dot_k)) via packed FFMA2.
    // Deviation vs exact = packed accumulation order only (~1e-7) << typical
    // 1st-2nd spacing near the min (~3e-3). Top-3 + exact rescore covers
    // quantized tie buckets (ulp(64)=7.6e-6) up to 3 members.
    const float FINF = __int_as_float(0x7f800000);
    float v00 = FINF, v01 = FINF, v02 = FINF;
    float v10 = FINF, v11 = FINF, v12 = FINF;
    int   x00 = 0, x01 = 0, x02 = 0;
    int   x10 = 0, x11 = 0, x12 = 0;

#pragma unroll 2
    for (int k = 0; k < KC; k += 4) {
        u64 a00 = 0ull, a01 = 0ull, a02 = 0ull, a03 = 0ull;  // token0
        u64 a10 = 0ull, a11 = 0ull, a12 = 0ull, a13 = 0ull;  // token1
        const ulonglong2* r0 = (const ulonglong2*)(s_cb + (k + 0) * DD);
        const ulonglong2* r1 = (const ulonglong2*)(s_cb + (k + 1) * DD);
        const ulonglong2* r2 = (const ulonglong2*)(s_cb + (k + 2) * DD);
        const ulonglong2* r3 = (const ulonglong2*)(s_cb + (k + 3) * DD);
#pragma unroll
        for (int i = 0; i < DD / 4; ++i) {
            ulonglong2 ca = r0[i], cbv = r1[i], cc = r2[i], cd = r3[i];
            u64 zl0 = zq0[2 * i], zh0 = zq0[2 * i + 1];
            u64 zl1 = zq1[2 * i], zh1 = zq1[2 * i + 1];
            a00 = ffma2(ca.x,  zl0, a00); a00 = ffma2(ca.y,  zh0, a00);
            a01 = ffma2(cbv.x, zl0, a01); a01 = ffma2(cbv.y, zh0, a01);
            a02 = ffma2(cc.x,  zl0, a02); a02 = ffma2(cc.y,  zh0, a02);
            a03 = ffma2(cd.x,  zl0, a03); a03 = ffma2(cd.y,  zh0, a03);
            a10 = ffma2(ca.x,  zl1, a10); a10 = ffma2(ca.y,  zh1, a10);
            a11 = ffma2(cbv.x, zl1, a11); a11 = ffma2(cbv.y, zh1, a11);
            a12 = ffma2(cc.x,  zl1, a12); a12 = ffma2(cc.y,  zh1, a12);
            a13 = ffma2(cd.x,  zl1, a13); a13 = ffma2(cd.y,  zh1, a13);
        }
        float c2a = s_c2[k + 0], c2b = s_c2[k + 1];
        float c2c = s_c2[k + 2], c2d = s_c2[k + 3];
        float2 p;
        p = unpack2(a00); top3(__fsub_rn(c2a, __fmul_rn(2.0f, __fadd_rn(p.x, p.y))), k + 0, v00, v01, v02, x00, x01, x02);
        p = unpack2(a01); top3(__fsub_rn(c2b, __fmul_rn(2.0f, __fadd_rn(p.x, p.y))), k + 1, v00, v01, v02, x00, x01, x02);
        p = unpack2(a02); top3(__fsub_rn(c2c, __fmul_rn(2.0f, __fadd_rn(p.x, p.y))), k + 2, v00, v01, v02, x00, x01, x02);
        p = unpack2(a03); top3(__fsub_rn(c2d, __fmul_rn(2.0f, __fadd_rn(p.x, p.y))), k + 3, v00, v01, v02, x00, x01, x02);
        p = unpack2(a10); top3(__fsub_rn(c2a, __fmul_rn(2.0f, __fadd_rn(p.x, p.y))), k + 0, v10, v11, v12, x10, x11, x12);
        p = unpack2(a11); top3(__fsub_rn(c2b, __fmul_rn(2.0f, __fadd_rn(p.x, p.y))), k + 1, v10, v11, v12, x10, x11, x12);
        p = unpack2(a12); top3(__fsub_rn(c2c, __fmul_rn(2.0f, __fadd_rn(p.x, p.y))), k + 2, v10, v11, v12, x10, x11, x12);
        p = unpack2(a13); top3(__fsub_rn(c2d, __fmul_rn(2.0f, __fadd_rn(p.x, p.y))), k + 3, v10, v11, v12, x10, x11, x12);
    }

    double dacc = (double)finish_token(zq0, tok0, s_cb, s_c2, out, x00, x01, x02)
                + (double)finish_token(zq1, tok1, s_cb, s_c2, out, x10, x11, x12);

    // Block reduce (double) -> global atomic -> last block finalizes + resets
#pragma unroll
    for (int o = 16; o > 0; o >>= 1)
        dacc += __shfl_down_sync(0xFFFFFFFFu, dacc, o);
    const int lane = threadIdx.x & 31;
    const int warp = threadIdx.x >> 5;
    if (lane == 0) s_red[warp] = dacc;
    __syncthreads();
    if (threadIdx.x == 0) {
        double t = 0.0;
#pragma unroll
        for (int w = 0; w < TPB / 32; ++w) t += s_red[w];
        atomicAdd(&g_loss_acc, t);
        __threadfence();
        unsigned int prev = atomicAdd(&g_done_ctr, 1u);
        if (prev == GRID - 1) {  // last block: finalize loss, reset for replay
            double m = atomicAdd(&g_loss_acc, 0.0) / (double)((long long)NT * DD);
            float m32 = (float)m;
            out[loss_idx] = __fadd_rn(m32, __fmul_rn(0.25f, m32));
            g_loss_acc = 0.0;
            __threadfence();
            g_done_ctr = 0u;
        }
    }
}

extern "C" void kernel_launch(void* const* d_in, const int* in_sizes, int n_in,
                              void* d_out, int out_size) {
    const float* z;
    const float* cb;
    if (in_sizes[0] == NT * DD) {
        z = (const float*)d_in[0];
        cb = (const float*)d_in[1];
    } else {
        z = (const float*)d_in[1];
        cb = (const float*)d_in[0];
    }
    float* out = (float*)d_out;

    cudaFuncSetAttribute(vq_fused, cudaFuncAttributeMaxDynamicSharedMemorySize,
                         SMEM_BYTES);
    vq_fused<<<GRID, TPB, SMEM_BYTES>>>(z, cb, out, out_size - 1);
}

// round 8
// speedup vs baseline: 1.2423x; 1.2423x over previous
#include <cuda_runtime.h>
#include <cuda_bf16.h>
#include <cstdint>

#define NT   262144
#define KC   512
#define DD   64
#define TPB  256
#define TK   128
#define GRID (NT / TK)
#define WIN  3.0e-3f
#define RS   72                         // smem row stride, bf16 units (144B)

#define OFF_Z    0
#define OFF_CB   (TK * RS * 2)          // 18432
#define OFF_C2   (OFF_CB + KC * RS * 2) // 92160
#define OFF_S    (OFF_C2 + KC * 4)      // 94208
#define OFF_CAND (OFF_S + TK * 4)       // 94720
#define OFF_RED  (OFF_CAND + TK * 8)    // 95744
#define SMEM_TOTAL (OFF_RED + 64)       // 95808 -> 2 CTAs/SM

typedef unsigned long long u64;

__device__ double g_loss_acc;
__device__ unsigned int g_done_ctr;

__device__ __forceinline__ void mma16816(float* d, const unsigned* a,
                                         unsigned b0, unsigned b1) {
    asm volatile(
        "mma.sync.aligned.m16n8k16.row.col.f32.bf16.bf16.f32 "
        "{%0,%1,%2,%3}, {%4,%5,%6,%7}, {%8,%9}, {%0,%1,%2,%3};"
        : "+f"(d[0]), "+f"(d[1]), "+f"(d[2]), "+f"(d[3])
        : "r"(a[0]), "r"(a[1]), "r"(a[2]), "r"(a[3]), "r"(b0), "r"(b1));
}

// Exact rescore (R2-proven rounding: fl(fl(S+c2)-fl(2*dot)), sequential
// ascending-d fp32 FMA) + packed atomicMin (equal e -> lower k = jnp ties).
__device__ __forceinline__ void rescore(const float* __restrict__ z,
                                        const float* __restrict__ cb,
                                        const float* s_c2, const float* s_S,
                                        u64* s_cand, size_t tok0, int row, int k) {
    const float4* rw = (const float4*)(cb + (size_t)k * DD);
    const float4* zr = (const float4*)(z + (tok0 + row) * DD);
    float d = 0.0f;
#pragma unroll
    for (int i = 0; i < DD / 4; ++i) {
        float4 a = rw[i], b = zr[i];
        d = __fmaf_rn(a.x, b.x, d); d = __fmaf_rn(a.y, b.y, d);
        d = __fmaf_rn(a.z, b.z, d); d = __fmaf_rn(a.w, b.w, d);
    }
    float e = __fsub_rn(__fadd_rn(s_S[row], s_c2[k]), __fmul_rn(2.0f, d));
    u64 pack = ((u64)__float_as_uint(e) << 32) | (unsigned)k;
    atomicMin(&s_cand[row], pack);
}

__global__ void __launch_bounds__(TPB, 2) vq_hmma(const float* __restrict__ z,
                                                  const float* __restrict__ cb,
                                                  float* __restrict__ out,
                                                  int loss_idx) {
    extern __shared__ char sm[];
    __nv_bfloat16* s_z  = (__nv_bfloat16*)(sm + OFF_Z);
    __nv_bfloat16* s_cb = (__nv_bfloat16*)(sm + OFF_CB);
    float* s_c2   = (float*)(sm + OFF_C2);
    float* s_S    = (float*)(sm + OFF_S);
    u64*   s_cand = (u64*)(sm + OFF_CAND);
    double* s_red = (double*)(sm + OFF_RED);

    const int tid = threadIdx.x, wid = tid >> 5, lane = tid & 31;
    const int g = lane >> 2, tg = lane & 3;
    const size_t tok0 = (size_t)blockIdx.x * TK;

    // ---- Load tiles (fp32 -> bf16, padded rows), norms, S, cand init ----
    {
        const float4* zf = (const float4*)(z + tok0 * DD);
        for (int idx = tid; idx < TK * DD / 4; idx += TPB) {
            int row = idx >> 4, c4 = idx & 15;
            float4 v = zf[idx];
            __nv_bfloat16* p = s_z + row * RS + c4 * 4;
            *(__nv_bfloat162*)(p)     = __floats2bfloat162_rn(v.x, v.y);
            *(__nv_bfloat162*)(p + 2) = __floats2bfloat162_rn(v.z, v.w);
        }
        const float4* cf = (const float4*)cb;
        for (int idx = tid; idx < KC * DD / 4; idx += TPB) {
            int row = idx >> 4, c4 = idx & 15;
            float4 v = cf[idx];
            __nv_bfloat16* p = s_cb + row * RS + c4 * 4;
            *(__nv_bfloat162*)(p)     = __floats2bfloat162_rn(v.x, v.y);
            *(__nv_bfloat162*)(p + 2) = __floats2bfloat162_rn(v.z, v.w);
        }
        for (int k = tid; k < KC; k += TPB) {     // exact fp32 norms
            const float4* r = (const float4*)(cb + (size_t)k * DD);
            float s = 0.0f;
#pragma unroll
            for (int i = 0; i < DD / 4; ++i) {
                float4 v = r[i];
                s = __fmaf_rn(v.x, v.x, s); s = __fmaf_rn(v.y, v.y, s);
                s = __fmaf_rn(v.z, v.z, s); s = __fmaf_rn(v.w, v.w, s);
            }
            s_c2[k] = s;
        }
        if (tid < TK) {                           // exact per-token S (shared!)
            const float4* r = (const float4*)(z + (tok0 + tid) * DD);
            float s = 0.0f;
#pragma unroll
            for (int i = 0; i < DD / 4; ++i) {
                float4 v = r[i];
                s = __fmaf_rn(v.x, v.x, s); s = __fmaf_rn(v.y, v.y, s);
                s = __fmaf_rn(v.z, v.z, s); s = __fmaf_rn(v.w, v.w, s);
            }
            s_S[tid] = s;
            s_cand[tid] = 0xFFFFFFFFFFFFFFFFull;
        }
    }
    __syncthreads();

    // ---- Persistent A fragments: warp w owns token rows 16w..16w+15 ----
    unsigned aF[4][4];
    const int rlo = wid * 16 + g;
#pragma unroll
    for (int ks = 0; ks < 4; ++ks) {
        const __nv_bfloat16* pl = s_z + rlo * RS + tg * 2 + 16 * ks;
        const __nv_bfloat16* ph = pl + 8 * RS;
        aF[ks][0] = *(const unsigned*)pl;
        aF[ks][1] = *(const unsigned*)ph;
        aF[ks][2] = *(const unsigned*)(pl + 8);
        aF[ks][3] = *(const unsigned*)(ph + 8);
    }

    const float FINF = __int_as_float(0x7f800000);
    float mn_lo = FINF, mn_hi = FINF;

    // ---- Pass 1: approx min per token ----
#pragma unroll 1
    for (int ch = 0; ch < 8; ++ch) {
        const int C0 = ch * 64;
        float acc[8][4];
#pragma unroll
        for (int j = 0; j < 8; ++j)
            acc[j][0] = acc[j][1] = acc[j][2] = acc[j][3] = 0.0f;
#pragma unroll
        for (int ks = 0; ks < 4; ++ks) {
#pragma unroll
            for (int j = 0; j < 8; ++j) {
                const __nv_bfloat16* bp = s_cb + (C0 + 8 * j + g) * RS + tg * 2 + 16 * ks;
                mma16816(acc[j], aF[ks], *(const unsigned*)bp, *(const unsigned*)(bp + 8));
            }
        }
#pragma unroll
        for (int j = 0; j < 8; ++j) {
            int c0 = C0 + 8 * j + tg * 2;
            float c2a = s_c2[c0], c2b = s_c2[c0 + 1];
            mn_lo = fminf(mn_lo, fminf(__fmaf_rn(-2.0f, acc[j][0], c2a),
                                       __fmaf_rn(-2.0f, acc[j][1], c2b)));
            mn_hi = fminf(mn_hi, fminf(__fmaf_rn(-2.0f, acc[j][2], c2a),
                                       __fmaf_rn(-2.0f, acc[j][3], c2b)));
        }
    }
    mn_lo = fminf(mn_lo, __shfl_xor_sync(0xFFFFFFFFu, mn_lo, 1));
    mn_lo = fminf(mn_lo, __shfl_xor_sync(0xFFFFFFFFu, mn_lo, 2));
    mn_hi = fminf(mn_hi, __shfl_xor_sync(0xFFFFFFFFu, mn_hi, 1));
    mn_hi = fminf(mn_hi, __shfl_xor_sync(0xFFFFFFFFu, mn_hi, 2));
    const float thr_lo = mn_lo + WIN, thr_hi = mn_hi + WIN;

    // ---- Pass 2: recompute, window-test, exact rescore of hits ----
#pragma unroll 1
    for (int ch = 0; ch < 8; ++ch) {
        const int C0 = ch * 64;
        float acc[8][4];
#pragma unroll
        for (int j = 0; j < 8; ++j)
            acc[j][0] = acc[j][1] = acc[j][2] = acc[j][3] = 0.0f;
#pragma unroll
        for (int ks = 0; ks < 4; ++ks) {
#pragma unroll
            for (int j = 0; j < 8; ++j) {
                const __nv_bfloat16* bp = s_cb + (C0 + 8 * j + g) * RS + tg * 2 + 16 * ks;
                mma16816(acc[j], aF[ks], *(const unsigned*)bp, *(const unsigned*)(bp + 8));
            }
        }
#pragma unroll
        for (int j = 0; j < 8; ++j) {
            int c0 = C0 + 8 * j + tg * 2;
            float c2a = s_c2[c0], c2b = s_c2[c0 + 1];
            float s0 = __fmaf_rn(-2.0f, acc[j][0], c2a);
            float s1 = __fmaf_rn(-2.0f, acc[j][1], c2b);
            float s2 = __fmaf_rn(-2.0f, acc[j][2], c2a);
            float s3 = __fmaf_rn(-2.0f, acc[j][3], c2b);
            if (s0 < thr_lo) rescore(z, cb, s_c2, s_S, s_cand, tok0, rlo,     c0);
            if (s1 < thr_lo) rescore(z, cb, s_c2, s_S, s_cand, tok0, rlo,     c0 + 1);
            if (s2 < thr_hi) rescore(z, cb, s_c2, s_S, s_cand, tok0, rlo + 8, c0);
            if (s3 < thr_hi) rescore(z, cb, s_c2, s_S, s_cand, tok0, rlo + 8, c0 + 1);
        }
    }
    __syncthreads();

    // ---- Epilogue (threads 0..127): STE output + loss partial ----
    double dacc = 0.0;
    if (tid < TK) {
        int bk = (int)(s_cand[tid] & 0xFFFFFFFFull);
        const float4* q  = (const float4*)(cb + (size_t)bk * DD);
        const float4* zr = (const float4*)(z + (tok0 + tid) * DD);
        float4* op = (float4*)(out + (tok0 + tid) * DD);
        float lacc = 0.0f;
#pragma unroll
        for (int i = 0; i < DD / 4; ++i) {
            float4 cv = q[i], zv = zr[i];
            float4 o; float dx;
            dx = __fsub_rn(cv.x, zv.x); o.x = __fadd_rn(zv.x, dx); lacc = __fmaf_rn(dx, dx, lacc);
            dx = __fsub_rn(cv.y, zv.y); o.y = __fadd_rn(zv.y, dx); lacc = __fmaf_rn(dx, dx, lacc);
            dx = __fsub_rn(cv.z, zv.z); o.z = __fadd_rn(zv.z, dx); lacc = __fmaf_rn(dx, dx, lacc);
            dx = __fsub_rn(cv.w, zv.w); o.w = __fadd_rn(zv.w, dx); lacc = __fmaf_rn(dx, dx, lacc);
            op[i] = o;
        }
        dacc = (double)lacc;
    }

#pragma unroll
    for (int o = 16; o > 0; o >>= 1)
        dacc += __shfl_down_sync(0xFFFFFFFFu, dacc, o);
    if (lane == 0) s_red[wid] = dacc;
    __syncthreads();
    if (tid == 0) {
        double t = 0.0;
#pragma unroll
        for (int w = 0; w < TPB / 32; ++w) t += s_red[w];
        atomicAdd(&g_loss_acc, t);
        __threadfence();
        unsigned int prev = atomicAdd(&g_done_ctr, 1u);
        if (prev == GRID - 1) {   // last block: finalize loss, reset for replay
            double m = atomicAdd(&g_loss_acc, 0.0) / (double)((long long)NT * DD);
            float m32 = (float)m;
            out[loss_idx] = __fadd_rn(m32, __fmul_rn(0.25f, m32));
            g_loss_acc = 0.0;
            __threadfence();
            g_done_ctr = 0u;
        }
    }
}

extern "C" void kernel_launch(void* const* d_in, const int* in_sizes, int n_in,
                              void* d_out, int out_size) {
    const float* z;
    const float* cb;
    if (in_sizes[0] == NT * DD) {
        z = (const float*)d_in[0];
        cb = (const float*)d_in[1];
    } else {
        z = (const float*)d_in[1];
        cb = (const float*)d_in[0];
    }
    float* out = (float*)d_out;

    cudaFuncSetAttribute(vq_hmma, cudaFuncAttributeMaxDynamicSharedMemorySize,
                         SMEM_TOTAL);
    vq_hmma<<<GRID, TPB, SMEM_TOTAL>>>(z, cb, out, out_size - 1);
}

// round 11
// speedup vs baseline: 1.3156x; 1.0590x over previous
#include <cuda_runtime.h>
#include <cuda_bf16.h>
#include <cstdint>

#define NT     262144
#define KC     512
#define DD     64
#define TPB    256
#define TK     128
#define NTILE  (NT / TK)      // 2048 token tiles
#define GRIDP  296            // persistent: 2 CTAs/SM x 148 SMs
#define WIN    3.0e-3f
#define RS     72             // smem row stride in bf16 (144B, conflict-free)

#define OFF_Z    0
#define OFF_CB   (TK * RS * 2)          // 18432
#define OFF_C2   (OFF_CB + KC * RS * 2) // 92160
#define OFF_S    (OFF_C2 + KC * 4)      // 94208
#define OFF_CAND (OFF_S + TK * 4)       // 94720
#define OFF_RED  (OFF_CAND + TK * 8)    // 95744
#define SMEM_TOTAL (OFF_RED + 64)       // 95808 -> 2 CTAs/SM

typedef unsigned long long u64;

__device__ double g_loss_acc;
__device__ unsigned int g_done_ctr;

__device__ __forceinline__ void mma16816(float* d, const unsigned* a,
                                         unsigned b0, unsigned b1) {
    asm volatile(
        "mma.sync.aligned.m16n8k16.row.col.f32.bf16.bf16.f32 "
        "{%0,%1,%2,%3}, {%4,%5,%6,%7}, {%8,%9}, {%0,%1,%2,%3};"
        : "+f"(d[0]), "+f"(d[1]), "+f"(d[2]), "+f"(d[3])
        : "r"(a[0]), "r"(a[1]), "r"(a[2]), "r"(a[3]), "r"(b0), "r"(b1));
}

// Exact rescore (R2-proven rounding: fl(fl(S+c2)-fl(2*dot)), sequential
// ascending-d fp32 FMA) + packed atomicMin (equal e -> lower k = jnp ties).
__device__ __forceinline__ void rescore(const float* __restrict__ z,
                                        const float* __restrict__ cb,
                                        const float* s_c2, const float* s_S,
                                        u64* s_cand, size_t tok0, int row, int k) {
    const float4* rw = (const float4*)(cb + (size_t)k * DD);
    const float4* zr = (const float4*)(z + (tok0 + row) * DD);
    float d = 0.0f;
#pragma unroll
    for (int i = 0; i < DD / 4; ++i) {
        float4 a = rw[i], b = zr[i];
        d = __fmaf_rn(a.x, b.x, d); d = __fmaf_rn(a.y, b.y, d);
        d = __fmaf_rn(a.z, b.z, d); d = __fmaf_rn(a.w, b.w, d);
    }
    float e = __fsub_rn(__fadd_rn(s_S[row], s_c2[k]), __fmul_rn(2.0f, d));
    u64 pack = ((u64)__float_as_uint(e) << 32) | (unsigned)k;
    atomicMin(&s_cand[row], pack);
}

__global__ void __launch_bounds__(TPB, 2) vq_pers(const float* __restrict__ z,
                                                  const float* __restrict__ cb,
                                                  float* __restrict__ out,
                                                  int loss_idx) {
    extern __shared__ char sm[];
    __nv_bfloat16* s_z  = (__nv_bfloat16*)(sm + OFF_Z);
    __nv_bfloat16* s_cb = (__nv_bfloat16*)(sm + OFF_CB);
    float* s_c2   = (float*)(sm + OFF_C2);
    float* s_S    = (float*)(sm + OFF_S);
    u64*   s_cand = (u64*)(sm + OFF_CAND);
    double* s_red = (double*)(sm + OFF_RED);

    const int tid = threadIdx.x, wid = tid >> 5, lane = tid & 31;
    const int g = lane >> 2, tg = lane & 3;
    const int rlo = wid * 16 + g;
    const float FINF = __int_as_float(0x7f800000);

    // ================= one-time: codebook bf16 tile + exact norms ==========
    {
        const float4* cf = (const float4*)cb;
        for (int idx = tid; idx < KC * DD / 4; idx += TPB) {
            int row = idx >> 4, c4 = idx & 15;
            float4 v = cf[idx];
            __nv_bfloat16* p = s_cb + row * RS + c4 * 4;
            *(__nv_bfloat162*)(p)     = __floats2bfloat162_rn(v.x, v.y);
            *(__nv_bfloat162*)(p + 2) = __floats2bfloat162_rn(v.z, v.w);
        }
        for (int k = tid; k < KC; k += TPB) {
            const float4* r = (const float4*)(cb + (size_t)k * DD);
            float s = 0.0f;
#pragma unroll
            for (int i = 0; i < DD / 4; ++i) {
                float4 v = r[i];
                s = __fmaf_rn(v.x, v.x, s); s = __fmaf_rn(v.y, v.y, s);
                s = __fmaf_rn(v.z, v.z, s); s = __fmaf_rn(v.w, v.w, s);
            }
            s_c2[k] = s;
        }
    }

    double my_loss = 0.0;

    // ================= persistent loop over token tiles ====================
    for (int tile = blockIdx.x; tile < NTILE; tile += GRIDP) {
        const size_t tok0 = (size_t)tile * TK;

        // ---- per-tile: z bf16 tile, exact S, candidate init ----
        {
            const float4* zf = (const float4*)(z + tok0 * DD);
            for (int idx = tid; idx < TK * DD / 4; idx += TPB) {
                int row = idx >> 4, c4 = idx & 15;
                float4 v = zf[idx];
                __nv_bfloat16* p = s_z + row * RS + c4 * 4;
                *(__nv_bfloat162*)(p)     = __floats2bfloat162_rn(v.x, v.y);
                *(__nv_bfloat162*)(p + 2) = __floats2bfloat162_rn(v.z, v.w);
            }
            if (tid < TK) {
                const float4* r = (const float4*)(z + (tok0 + tid) * DD);
                float s = 0.0f;
#pragma unroll
                for (int i = 0; i < DD / 4; ++i) {
                    float4 v = r[i];
                    s = __fmaf_rn(v.x, v.x, s); s = __fmaf_rn(v.y, v.y, s);
                    s = __fmaf_rn(v.z, v.z, s); s = __fmaf_rn(v.w, v.w, s);
                }
                s_S[tid] = s;
                s_cand[tid] = 0xFFFFFFFFFFFFFFFFull;
            }
        }
        __syncthreads();

        // ---- persistent A fragments: warp w owns rows 16w..16w+15 ----
        unsigned aF[4][4];
#pragma unroll
        for (int ks = 0; ks < 4; ++ks) {
            const __nv_bfloat16* pl = s_z + rlo * RS + tg * 2 + 16 * ks;
            const __nv_bfloat16* ph = pl + 8 * RS;
            aF[ks][0] = *(const unsigned*)pl;
            aF[ks][1] = *(const unsigned*)ph;
            aF[ks][2] = *(const unsigned*)(pl + 8);
            aF[ks][3] = *(const unsigned*)(ph + 8);
        }

        float mn_lo = FINF, mn_hi = FINF;

        // ---- Pass 1: approx min per token ----
#pragma unroll 1
        for (int ch = 0; ch < 8; ++ch) {
            const int C0 = ch * 64;
            float acc[8][4];
#pragma unroll
            for (int j = 0; j < 8; ++j)
                acc[j][0] = acc[j][1] = acc[j][2] = acc[j][3] = 0.0f;
#pragma unroll
            for (int ks = 0; ks < 4; ++ks) {
#pragma unroll
                for (int j = 0; j < 8; ++j) {
                    const __nv_bfloat16* bp =
                        s_cb + (C0 + 8 * j + g) * RS + tg * 2 + 16 * ks;
                    mma16816(acc[j], aF[ks],
                             *(const unsigned*)bp, *(const unsigned*)(bp + 8));
                }
            }
#pragma unroll
            for (int j = 0; j < 8; ++j) {
                int c0 = C0 + 8 * j + tg * 2;
                float c2a = s_c2[c0], c2b = s_c2[c0 + 1];
                mn_lo = fminf(mn_lo, fminf(__fmaf_rn(-2.0f, acc[j][0], c2a),
                                           __fmaf_rn(-2.0f, acc[j][1], c2b)));
                mn_hi = fminf(mn_hi, fminf(__fmaf_rn(-2.0f, acc[j][2], c2a),
                                           __fmaf_rn(-2.0f, acc[j][3], c2b)));
            }
        }
        mn_lo = fminf(mn_lo, __shfl_xor_sync(0xFFFFFFFFu, mn_lo, 1));
        mn_lo = fminf(mn_lo, __shfl_xor_sync(0xFFFFFFFFu, mn_lo, 2));
        mn_hi = fminf(mn_hi, __shfl_xor_sync(0xFFFFFFFFu, mn_hi, 1));
        mn_hi = fminf(mn_hi, __shfl_xor_sync(0xFFFFFFFFu, mn_hi, 2));
        const float thr_lo = mn_lo + WIN, thr_hi = mn_hi + WIN;

        // ---- Pass 2: recompute, window-test, exact rescore of hits ----
#pragma unroll 1
        for (int ch = 0; ch < 8; ++ch) {
            const int C0 = ch * 64;
            float acc[8][4];
#pragma unroll
            for (int j = 0; j < 8; ++j)
                acc[j][0] = acc[j][1] = acc[j][2] = acc[j][3] = 0.0f;
#pragma unroll
            for (int ks = 0; ks < 4; ++ks) {
#pragma unroll
                for (int j = 0; j < 8; ++j) {
                    const __nv_bfloat16* bp =
                        s_cb + (C0 + 8 * j + g) * RS + tg * 2 + 16 * ks;
                    mma16816(acc[j], aF[ks],
                             *(const unsigned*)bp, *(const unsigned*)(bp + 8));
                }
            }
#pragma unroll
            for (int j = 0; j < 8; ++j) {
                int c0 = C0 + 8 * j + tg * 2;
                float c2a = s_c2[c0], c2b = s_c2[c0 + 1];
                float s0 = __fmaf_rn(-2.0f, acc[j][0], c2a);
                float s1 = __fmaf_rn(-2.0f, acc[j][1], c2b);
                float s2 = __fmaf_rn(-2.0f, acc[j][2], c2a);
                float s3 = __fmaf_rn(-2.0f, acc[j][3], c2b);
                if (s0 < thr_lo) rescore(z, cb, s_c2, s_S, s_cand, tok0, rlo,     c0);
                if (s1 < thr_lo) rescore(z, cb, s_c2, s_S, s_cand, tok0, rlo,     c0 + 1);
                if (s2 < thr_hi) rescore(z, cb, s_c2, s_S, s_cand, tok0, rlo + 8, c0);
                if (s3 < thr_hi) rescore(z, cb, s_c2, s_S, s_cand, tok0, rlo + 8, c0 + 1);
            }
        }
        __syncthreads();

        // ---- Epilogue (threads 0..127): STE output + loss partial ----
        if (tid < TK) {
            int bk = (int)(s_cand[tid] & 0xFFFFFFFFull);
            const float4* q  = (const float4*)(cb + (size_t)bk * DD);
            const float4* zr = (const float4*)(z + (tok0 + tid) * DD);
            float4* op = (float4*)(out + (tok0 + tid) * DD);
            float lacc = 0.0f;
#pragma unroll
            for (int i = 0; i < DD / 4; ++i) {
                float4 cv = q[i], zv = zr[i];
                float4 o; float dx;
                dx = __fsub_rn(cv.x, zv.x); o.x = __fadd_rn(zv.x, dx); lacc = __fmaf_rn(dx, dx, lacc);
                dx = __fsub_rn(cv.y, zv.y); o.y = __fadd_rn(zv.y, dx); lacc = __fmaf_rn(dx, dx, lacc);
                dx = __fsub_rn(cv.z, zv.z); o.z = __fadd_rn(zv.z, dx); lacc = __fmaf_rn(dx, dx, lacc);
                dx = __fsub_rn(cv.w, zv.w); o.w = __fadd_rn(zv.w, dx); lacc = __fmaf_rn(dx, dx, lacc);
                op[i] = o;
            }
            my_loss += (double)lacc;
        }
        __syncthreads();   // protect s_cand / s_z / s_S reuse next tile
    }

    // ================= final: reduce loss once per CTA =====================
    double dacc = my_loss;
#pragma unroll
    for (int o = 16; o > 0; o >>= 1)
        dacc += __shfl_down_sync(0xFFFFFFFFu, dacc, o);
    if (lane == 0) s_red[wid] = dacc;
    __syncthreads();
    if (tid == 0) {
        double t = 0.0;
#pragma unroll
        for (int w = 0; w < TPB / 32; ++w) t += s_red[w];
        atomicAdd(&g_loss_acc, t);
        __threadfence();
        unsigned int prev = atomicAdd(&g_done_ctr, 1u);
        if (prev == GRIDP - 1) {  // last CTA: finalize loss, reset for replay
            double m = atomicAdd(&g_loss_acc, 0.0) / (double)((long long)NT * DD);
            float m32 = (float)m;
            out[loss_idx] = __fadd_rn(m32, __fmul_rn(0.25f, m32));
            g_loss_acc = 0.0;
            __threadfence();
            g_done_ctr = 0u;
        }
    }
}

extern "C" void kernel_launch(void* const* d_in, const int* in_sizes, int n_in,
                              void* d_out, int out_size) {
    const float* z;
    const float* cb;
    if (in_sizes[0] == NT * DD) {
        z = (const float*)d_in[0];
        cb = (const float*)d_in[1];
    } else {
        z = (const float*)d_in[1];
        cb = (const float*)d_in[0];
    }
    float* out = (float*)d_out;

    cudaFuncSetAttribute(vq_pers, cudaFuncAttributeMaxDynamicSharedMemorySize,
                         SMEM_TOTAL);
    vq_pers<<<GRIDP, TPB, SMEM_TOTAL>>>(z, cb, out, out_size - 1);
}

// round 12
// speedup vs baseline: 2.2833x; 1.7356x over previous
#include <cuda_runtime.h>
#include <cuda_bf16.h>
#include <cstdint>

#define NT     262144
#define KC     512
#define DD     64
#define TPB    256
#define TK     128
#define NTILE  (NT / TK)
#define GRIDP  296
#define WIN    3.0e-3f
#define RS     72            // z-tile row stride in bf16 (144B)
#define QCAP   1024

#define OFF_Z    0                       // 18432
#define OFF_CBP  18432                   // packed codebook 512*144 = 73728
#define OFF_C2   (OFF_CBP + 73728)       // 92160: fp32 norms [512]
#define OFF_S    (OFF_C2 + 2048)         // 94208: per-token S [128]
#define OFF_CAND (OFF_S + 512)           // 94720: packed (e,k) [128] u64
#define OFF_Q    (OFF_CAND + 1024)       // 95744: hit queue u32 [1024]
#define OFF_QC   (OFF_Q + 4096)          // 99840: queue count
#define OFF_RED  (OFF_QC + 16)           // 99856: loss partials
#define SMEM_TOTAL (OFF_RED + 64)        // 99920 -> 2 CTAs/SM

typedef unsigned long long u64;

__device__ double g_loss_acc;
__device__ unsigned int g_done_ctr;

__device__ __forceinline__ void mma16816(float* d, const unsigned* a,
                                         unsigned b0, unsigned b1) {
    asm volatile(
        "mma.sync.aligned.m16n8k16.row.col.f32.bf16.bf16.f32 "
        "{%0,%1,%2,%3}, {%4,%5,%6,%7}, {%8,%9}, {%0,%1,%2,%3};"
        : "+f"(d[0]), "+f"(d[1]), "+f"(d[2]), "+f"(d[3])
        : "r"(a[0]), "r"(a[1]), "r"(a[2]), "r"(a[3]), "r"(b0), "r"(b1));
}

// Exact rescore (R2-proven rounding: fl(fl(S+c2)-fl(2*dot)), sequential
// ascending-d fp32 FMA) + packed atomicMin (equal e -> lower k = jnp ties).
__device__ __forceinline__ void rescore(const float* __restrict__ z,
                                        const float* __restrict__ cb,
                                        const float* s_c2, const float* s_S,
                                        u64* s_cand, size_t tok0, int row, int k) {
    const float4* rw = (const float4*)(cb + (size_t)k * DD);
    const float4* zr = (const float4*)(z + (tok0 + row) * DD);
    float d = 0.0f;
#pragma unroll
    for (int i = 0; i < DD / 4; ++i) {
        float4 a = rw[i], b = zr[i];
        d = __fmaf_rn(a.x, b.x, d); d = __fmaf_rn(a.y, b.y, d);
        d = __fmaf_rn(a.z, b.z, d); d = __fmaf_rn(a.w, b.w, d);
    }
    float e = __fsub_rn(__fadd_rn(s_S[row], s_c2[k]), __fmul_rn(2.0f, d));
    u64 pack = ((u64)__float_as_uint(e) << 32) | (unsigned)k;
    atomicMin(&s_cand[row], pack);
}

__global__ void __launch_bounds__(TPB, 2) vq_pipe(const float* __restrict__ z,
                                                  const float* __restrict__ cb,
                                                  float* __restrict__ out,
                                                  int loss_idx) {
    extern __shared__ char sm[];
    __nv_bfloat16* s_z = (__nv_bfloat16*)(sm + OFF_Z);
    float*  s_c2   = (float*)(sm + OFF_C2);
    float2* s_c2p  = (float2*)(sm + OFF_C2);
    float*  s_S    = (float*)(sm + OFF_S);
    u64*    s_cand = (u64*)(sm + OFF_CAND);
    unsigned* s_q  = (unsigned*)(sm + OFF_Q);
    int*    s_qc   = (int*)(sm + OFF_QC);
    double* s_red  = (double*)(sm + OFF_RED);

    const int tid = threadIdx.x, wid = tid >> 5, lane = tid & 31;
    const int g = lane >> 2, tg = lane & 3;
    const int rlo = wid * 16 + g;
    const float FINF = __int_as_float(0x7f800000);

    // ---- one-time: pair-packed bf16 codebook + exact fp32 norms ----
    // Packed unit for (code n, k-step ks, lane tg): 8 bytes holding
    // (b0,b1) = bf16x2 at cols {16ks+2tg, +1} and {16ks+2tg+8, +9}.
    // Row stride 144B -> LDS.64 per MMA, 2-wavefront optimal.
    {
        const float4* cf = (const float4*)cb;
        for (int idx = tid; idx < KC * DD / 4; idx += TPB) {
            int n = idx >> 4, c4 = idx & 15;
            float4 v = cf[idx];
            int k0 = c4 * 4;
            int ks = k0 >> 4;
            int r0 = k0 & 15, r1 = r0 + 2;
            char* base = sm + OFF_CBP + n * 144 + ks * 32;
            *(__nv_bfloat162*)(base + ((r0 >> 1) & 3) * 8 + (r0 >> 3) * 4) =
                __floats2bfloat162_rn(v.x, v.y);
            *(__nv_bfloat162*)(base + ((r1 >> 1) & 3) * 8 + (r1 >> 3) * 4) =
                __floats2bfloat162_rn(v.z, v.w);
        }
        for (int k = tid; k < KC; k += TPB) {
            const float4* r = (const float4*)(cb + (size_t)k * DD);
            float s = 0.0f;
#pragma unroll
            for (int i = 0; i < DD / 4; ++i) {
                float4 v = r[i];
                s = __fmaf_rn(v.x, v.x, s); s = __fmaf_rn(v.y, v.y, s);
                s = __fmaf_rn(v.z, v.z, s); s = __fmaf_rn(v.w, v.w, s);
            }
            s_c2[k] = s;
        }
    }

    const char* pb = sm + OFF_CBP + g * 144 + tg * 8;  // lane-constant base
    double my_loss = 0.0;

    for (int tile = blockIdx.x; tile < NTILE; tile += GRIDP) {
        const size_t tok0 = (size_t)tile * TK;

        // ---- per-tile init: z bf16 tile, exact S, cand, queue ----
        {
            const float4* zf = (const float4*)(z + tok0 * DD);
            for (int idx = tid; idx < TK * DD / 4; idx += TPB) {
                int row = idx >> 4, c4 = idx & 15;
                float4 v = zf[idx];
                __nv_bfloat16* p = s_z + row * RS + c4 * 4;
                *(__nv_bfloat162*)(p)     = __floats2bfloat162_rn(v.x, v.y);
                *(__nv_bfloat162*)(p + 2) = __floats2bfloat162_rn(v.z, v.w);
            }
            if (tid < TK) {
                const float4* r = (const float4*)(z + (tok0 + tid) * DD);
                float s = 0.0f;
#pragma unroll
                for (int i = 0; i < DD / 4; ++i) {
                    float4 v = r[i];
                    s = __fmaf_rn(v.x, v.x, s); s = __fmaf_rn(v.y, v.y, s);
                    s = __fmaf_rn(v.z, v.z, s); s = __fmaf_rn(v.w, v.w, s);
                }
                s_S[tid] = s;
                s_cand[tid] = 0xFFFFFFFFFFFFFFFFull;
            }
            if (tid == 0) *s_qc = 0;
        }
        __syncthreads();

        // ---- A fragments (proven layout) ----
        unsigned aF[4][4];
#pragma unroll
        for (int ks = 0; ks < 4; ++ks) {
            const __nv_bfloat16* pl = s_z + rlo * RS + tg * 2 + 16 * ks;
            const __nv_bfloat16* ph = pl + 8 * RS;
            aF[ks][0] = *(const unsigned*)pl;
            aF[ks][1] = *(const unsigned*)ph;
            aF[ks][2] = *(const unsigned*)(pl + 8);
            aF[ks][3] = *(const unsigned*)(ph + 8);
        }

        float mA_lo = FINF, mB_lo = FINF, mA_hi = FINF, mB_hi = FINF;

        // ---- Pass 1: pipelined MMA, split min chains ----
#pragma unroll 1
        for (int ch = 0; ch < 8; ++ch) {
            const char* pc = pb + ch * 9216;
            uint2 bA[8], bB[8];
            float acc[8][4];
#pragma unroll
            for (int j = 0; j < 8; ++j) {
                bA[j] = *(const uint2*)(pc + j * 1152);
                acc[j][0] = acc[j][1] = acc[j][2] = acc[j][3] = 0.0f;
            }
#pragma unroll
            for (int ks = 0; ks < 4; ++ks) {
                uint2* cur = (ks & 1) ? bB : bA;
                uint2* nxt = (ks & 1) ? bA : bB;
                if (ks < 3) {
#pragma unroll
                    for (int j = 0; j < 8; ++j)
                        nxt[j] = *(const uint2*)(pc + j * 1152 + (ks + 1) * 32);
                }
#pragma unroll
                for (int j = 0; j < 8; ++j)
                    mma16816(acc[j], aF[ks], cur[j].x, cur[j].y);
            }
            const int C0 = ch * 64;
#pragma unroll
            for (int j = 0; j < 8; ++j) {
                int c0 = C0 + 8 * j + tg * 2;
                float2 cc = s_c2p[c0 >> 1];
                float sl = fminf(__fmaf_rn(-2.0f, acc[j][0], cc.x),
                                 __fmaf_rn(-2.0f, acc[j][1], cc.y));
                float sh = fminf(__fmaf_rn(-2.0f, acc[j][2], cc.x),
                                 __fmaf_rn(-2.0f, acc[j][3], cc.y));
                if (j & 1) { mB_lo = fminf(mB_lo, sl); mB_hi = fminf(mB_hi, sh); }
                else       { mA_lo = fminf(mA_lo, sl); mA_hi = fminf(mA_hi, sh); }
            }
        }
        float mn_lo = fminf(mA_lo, mB_lo), mn_hi = fminf(mA_hi, mB_hi);
        mn_lo = fminf(mn_lo, __shfl_xor_sync(0xFFFFFFFFu, mn_lo, 1));
        mn_lo = fminf(mn_lo, __shfl_xor_sync(0xFFFFFFFFu, mn_lo, 2));
        mn_hi = fminf(mn_hi, __shfl_xor_sync(0xFFFFFFFFu, mn_hi, 1));
        mn_hi = fminf(mn_hi, __shfl_xor_sync(0xFFFFFFFFu, mn_hi, 2));
        const float thr_lo = mn_lo + WIN, thr_hi = mn_hi + WIN;

        // ---- Pass 2: recompute, push window hits to queue ----
#pragma unroll 1
        for (int ch = 0; ch < 8; ++ch) {
            const char* pc = pb + ch * 9216;
            uint2 bA[8], bB[8];
            float acc[8][4];
#pragma unroll
            for (int j = 0; j < 8; ++j) {
                bA[j] = *(const uint2*)(pc + j * 1152);
                acc[j][0] = acc[j][1] = acc[j][2] = acc[j][3] = 0.0f;
            }
#pragma unroll
            for (int ks = 0; ks < 4; ++ks) {
                uint2* cur = (ks & 1) ? bB : bA;
                uint2* nxt = (ks & 1) ? bA : bB;
                if (ks < 3) {
#pragma unroll
                    for (int j = 0; j < 8; ++j)
                        nxt[j] = *(const uint2*)(pc + j * 1152 + (ks + 1) * 32);
                }
#pragma unroll
                for (int j = 0; j < 8; ++j)
                    mma16816(acc[j], aF[ks], cur[j].x, cur[j].y);
            }
            const int C0 = ch * 64;
#pragma unroll
            for (int j = 0; j < 8; ++j) {
                int c0 = C0 + 8 * j + tg * 2;
                float2 cc = s_c2p[c0 >> 1];
                float s0 = __fmaf_rn(-2.0f, acc[j][0], cc.x);
                float s1 = __fmaf_rn(-2.0f, acc[j][1], cc.y);
                float s2 = __fmaf_rn(-2.0f, acc[j][2], cc.x);
                float s3 = __fmaf_rn(-2.0f, acc[j][3], cc.y);
                if (s0 < thr_lo) { int sl = atomicAdd(s_qc, 1); if (sl < QCAP) s_q[sl] = (unsigned)((rlo << 9) | c0); }
                if (s1 < thr_lo) { int sl = atomicAdd(s_qc, 1); if (sl < QCAP) s_q[sl] = (unsigned)((rlo << 9) | (c0 + 1)); }
                if (s2 < thr_hi) { int sl = atomicAdd(s_qc, 1); if (sl < QCAP) s_q[sl] = (unsigned)(((rlo + 8) << 9) | c0); }
                if (s3 < thr_hi) { int sl = atomicAdd(s_qc, 1); if (sl < QCAP) s_q[sl] = (unsigned)(((rlo + 8) << 9) | (c0 + 1)); }
            }
        }
        __syncthreads();

        // ---- Drain queue: cooperative exact rescore ----
        {
            int nq = *s_qc;
            if (nq > QCAP) {
                // overflow (prob ~0): full exact scan per token, still correct
                if (tid < TK) {
                    float S = s_S[tid];
                    u64 best = 0xFFFFFFFFFFFFFFFFull;
                    for (int k = 0; k < KC; ++k) {
                        const float4* rw = (const float4*)(cb + (size_t)k * DD);
                        const float4* zr = (const float4*)(z + (tok0 + tid) * DD);
                        float d = 0.0f;
#pragma unroll
                        for (int i = 0; i < DD / 4; ++i) {
                            float4 a = rw[i], b = zr[i];
                            d = __fmaf_rn(a.x, b.x, d); d = __fmaf_rn(a.y, b.y, d);
                            d = __fmaf_rn(a.z, b.z, d); d = __fmaf_rn(a.w, b.w, d);
                        }
                        float e = __fsub_rn(__fadd_rn(S, s_c2[k]), __fmul_rn(2.0f, d));
                        u64 p = ((u64)__float_as_uint(e) << 32) | (unsigned)k;
                        if (p < best) best = p;
                    }
                    atomicMin(&s_cand[tid], best);
                }
            } else {
                for (int i = tid; i < nq; i += TPB) {
                    unsigned e = s_q[i];
                    rescore(z, cb, s_c2, s_S, s_cand, tok0, (int)(e >> 9), (int)(e & 511u));
                }
            }
        }
        __syncthreads();

        // ---- Epilogue (threads 0..127): STE output + loss partial ----
        if (tid < TK) {
            int bk = (int)(s_cand[tid] & 0xFFFFFFFFull);
            const float4* q  = (const float4*)(cb + (size_t)bk * DD);
            const float4* zr = (const float4*)(z + (tok0 + tid) * DD);
            float4* op = (float4*)(out + (tok0 + tid) * DD);
            float lacc = 0.0f;
#pragma unroll
            for (int i = 0; i < DD / 4; ++i) {
                float4 cv = q[i], zv = zr[i];
                float4 o; float dx;
                dx = __fsub_rn(cv.x, zv.x); o.x = __fadd_rn(zv.x, dx); lacc = __fmaf_rn(dx, dx, lacc);
                dx = __fsub_rn(cv.y, zv.y); o.y = __fadd_rn(zv.y, dx); lacc = __fmaf_rn(dx, dx, lacc);
                dx = __fsub_rn(cv.z, zv.z); o.z = __fadd_rn(zv.z, dx); lacc = __fmaf_rn(dx, dx, lacc);
                dx = __fsub_rn(cv.w, zv.w); o.w = __fadd_rn(zv.w, dx); lacc = __fmaf_rn(dx, dx, lacc);
                op[i] = o;
            }
            my_loss += (double)lacc;
        }
        __syncthreads();
    }

    // ---- final loss reduction ----
    double dacc = my_loss;
#pragma unroll
    for (int o = 16; o > 0; o >>= 1)
        dacc += __shfl_down_sync(0xFFFFFFFFu, dacc, o);
    if (lane == 0) s_red[wid] = dacc;
    __syncthreads();
    if (tid == 0) {
        double t = 0.0;
#pragma unroll
        for (int w = 0; w < TPB / 32; ++w) t += s_red[w];
        atomicAdd(&g_loss_acc, t);
        __threadfence();
        unsigned int prev = atomicAdd(&g_done_ctr, 1u);
        if (prev == GRIDP - 1) {
            double m = atomicAdd(&g_loss_acc, 0.0) / (double)((long long)NT * DD);
            float m32 = (float)m;
            out[loss_idx] = __fadd_rn(m32, __fmul_rn(0.25f, m32));
            g_loss_acc = 0.0;
            __threadfence();
            g_done_ctr = 0u;
        }
    }
}

extern "C" void kernel_launch(void* const* d_in, const int* in_sizes, int n_in,
                              void* d_out, int out_size) {
    const float* z;
    const float* cb;
    if (in_sizes[0] == NT * DD) {
        z = (const float*)d_in[0];
        cb = (const float*)d_in[1];
    } else {
        z = (const float*)d_in[1];
        cb = (const float*)d_in[0];
    }
    float* out = (float*)d_out;

    cudaFuncSetAttribute(vq_pipe, cudaFuncAttributeMaxDynamicSharedMemorySize,
                         SMEM_TOTAL);
    vq_pipe<<<GRIDP, TPB, SMEM_TOTAL>>>(z, cb, out, out_size - 1);
}

// round 13
// speedup vs baseline: 2.7596x; 1.2086x over previous
#include <cuda_runtime.h>
#include <cuda_bf16.h>
#include <cstdint>

#define NT     262144
#define KC     512
#define DD     64
#define TPB    256
#define TK     128
#define NTILE  (NT / TK)
#define GRIDP  296
#define WIN    3.0e-3f
#define QCAP   1024

// smem layout
#define OFF_A    0                      // packed A frags: 8 mt-blocks * 4 ks * 512B = 16384
#define OFF_CBP  16384                  // pair-packed codebook 512*144 = 73728
#define OFF_C2   (OFF_CBP + 73728)      // 90112: fp32 norms [512]
#define OFF_S    (OFF_C2 + 2048)        // 92160: per-token S [128]
#define OFF_CAND (OFF_S + 512)          // 92672: packed (e,k) [128] u64
#define OFF_MINW (OFF_CAND + 1024)      // 93696: per-token per-cgrp mins [128][2] f32
#define OFF_Q    (OFF_MINW + 1024)      // 94720: hit queue u32 [1024]
#define OFF_QC   (OFF_Q + 4096)         // 98816
#define OFF_RED  (OFF_QC + 16)          // 98832
#define SMEM_TOTAL (OFF_RED + 64)       // 98896 -> 2 CTAs/SM

typedef unsigned long long u64;

__device__ double g_loss_acc;
__device__ unsigned int g_done_ctr;

__device__ __forceinline__ void mma16816(float* d, const unsigned* a,
                                         unsigned b0, unsigned b1) {
    asm volatile(
        "mma.sync.aligned.m16n8k16.row.col.f32.bf16.bf16.f32 "
        "{%0,%1,%2,%3}, {%4,%5,%6,%7}, {%8,%9}, {%0,%1,%2,%3};"
        : "+f"(d[0]), "+f"(d[1]), "+f"(d[2]), "+f"(d[3])
        : "r"(a[0]), "r"(a[1]), "r"(a[2]), "r"(a[3]), "r"(b0), "r"(b1));
}

__device__ __forceinline__ unsigned pk2(float x, float y) {
    __nv_bfloat162 b = __floats2bfloat162_rn(x, y);
    return *(unsigned*)&b;
}

// Exact rescore (R2-proven rounding: fl(fl(S+c2)-fl(2*dot)), sequential
// ascending-d fp32 FMA) + packed atomicMin (equal e -> lower k = jnp ties).
__device__ __forceinline__ void rescore(const float* __restrict__ z,
                                        const float* __restrict__ cb,
                                        const float* s_c2, const float* s_S,
                                        u64* s_cand, size_t tok0, int row, int k) {
    const float4* rw = (const float4*)(cb + (size_t)k * DD);
    const float4* zr = (const float4*)(z + (tok0 + row) * DD);
    float d = 0.0f;
#pragma unroll
    for (int i = 0; i < DD / 4; ++i) {
        float4 a = rw[i], b = zr[i];
        d = __fmaf_rn(a.x, b.x, d); d = __fmaf_rn(a.y, b.y, d);
        d = __fmaf_rn(a.z, b.z, d); d = __fmaf_rn(a.w, b.w, d);
    }
    float e = __fsub_rn(__fadd_rn(s_S[row], s_c2[k]), __fmul_rn(2.0f, d));
    u64 pack = ((u64)__float_as_uint(e) << 32) | (unsigned)k;
    atomicMin(&s_cand[row], pack);
}

__global__ void __launch_bounds__(TPB, 2) vq_split(const float* __restrict__ z,
                                                   const float* __restrict__ cb,
                                                   float* __restrict__ out,
                                                   int loss_idx) {
    extern __shared__ char sm[];
    float*  s_c2   = (float*)(sm + OFF_C2);
    float2* s_c2p  = (float2*)(sm + OFF_C2);
    float*  s_S    = (float*)(sm + OFF_S);
    u64*    s_cand = (u64*)(sm + OFF_CAND);
    float*  s_minw = (float*)(sm + OFF_MINW);
    unsigned* s_q  = (unsigned*)(sm + OFF_Q);
    int*    s_qc   = (int*)(sm + OFF_QC);
    double* s_red  = (double*)(sm + OFF_RED);

    const int tid = threadIdx.x, wid = tid >> 5, lane = tid & 31;
    const int g = lane >> 2, tg = lane & 3;
    const int tgrp = wid >> 1;        // token group: 32 tokens each (4 groups)
    const int cgrp = wid & 1;         // code group: 256 codes each (2 groups)
    const float FINF = __int_as_float(0x7f800000);

    // ---- one-time: pair-packed bf16 codebook + exact fp32 norms (R12 layout) ----
    {
        const float4* cf = (const float4*)cb;
        for (int idx = tid; idx < KC * DD / 4; idx += TPB) {
            int n = idx >> 4, c4 = idx & 15;
            float4 v = cf[idx];
            int k0 = c4 * 4;
            int ks = k0 >> 4;
            int r0 = k0 & 15, r1 = r0 + 2;
            char* base = sm + OFF_CBP + n * 144 + ks * 32;
            *(__nv_bfloat162*)(base + ((r0 >> 1) & 3) * 8 + (r0 >> 3) * 4) =
                __floats2bfloat162_rn(v.x, v.y);
            *(__nv_bfloat162*)(base + ((r1 >> 1) & 3) * 8 + (r1 >> 3) * 4) =
                __floats2bfloat162_rn(v.z, v.w);
        }
        for (int k = tid; k < KC; k += TPB) {
            const float4* r = (const float4*)(cb + (size_t)k * DD);
            float s = 0.0f;
#pragma unroll
            for (int i = 0; i < DD / 4; ++i) {
                float4 v = r[i];
                s = __fmaf_rn(v.x, v.x, s); s = __fmaf_rn(v.y, v.y, s);
                s = __fmaf_rn(v.z, v.z, s); s = __fmaf_rn(v.w, v.w, s);
            }
            s_c2[k] = s;
        }
    }

    double my_loss = 0.0;

    for (int tile = blockIdx.x; tile < NTILE; tile += GRIDP) {
        const size_t tok0 = (size_t)tile * TK;

        // ---- per-tile: fragment-packed A (z) tile, exact S, cand, queue ----
        // A unit (mtg = grp*2+mt, ks, lane): 16B = {z[r,c..c+1], z[r+8,c..c+1],
        //  z[r,c+8..c+9], z[r+8,c+8..c+9]}, r = (mtg>>1)*32+(mtg&1)*16+g, c=16ks+2tg.
#pragma unroll 1
        for (int u = tid; u < 1024; u += TPB) {
            int lane_u = u & 31, ks = (u >> 5) & 3, mtg = u >> 7;
            int gg = lane_u >> 2, tgg = lane_u & 3;
            int r = (mtg >> 1) * 32 + (mtg & 1) * 16 + gg;
            int c = ks * 16 + tgg * 2;
            const float* zb = z + (tok0 + r) * DD + c;
            float2 v0 = *(const float2*)(zb);
            float2 v1 = *(const float2*)(zb + 8 * DD);
            float2 v2 = *(const float2*)(zb + 8);
            float2 v3 = *(const float2*)(zb + 8 * DD + 8);
            uint4 pk;
            pk.x = pk2(v0.x, v0.y); pk.y = pk2(v1.x, v1.y);
            pk.z = pk2(v2.x, v2.y); pk.w = pk2(v3.x, v3.y);
            *(uint4*)(sm + OFF_A + u * 16) = pk;
        }
        if (tid < TK) {
            const float4* r = (const float4*)(z + (tok0 + tid) * DD);
            float s = 0.0f;
#pragma unroll
            for (int i = 0; i < DD / 4; ++i) {
                float4 v = r[i];
                s = __fmaf_rn(v.x, v.x, s); s = __fmaf_rn(v.y, v.y, s);
                s = __fmaf_rn(v.z, v.z, s); s = __fmaf_rn(v.w, v.w, s);
            }
            s_S[tid] = s;
            s_cand[tid] = 0xFFFFFFFFFFFFFFFFull;
        }
        if (tid == 0) *s_qc = 0;
        __syncthreads();

        // ---- A fragments for this warp's 32 rows: held across both passes ----
        unsigned aF[2][4][4];
#pragma unroll
        for (int mt = 0; mt < 2; ++mt)
#pragma unroll
            for (int ks = 0; ks < 4; ++ks) {
                uint4 t = *(const uint4*)(sm + OFF_A +
                    (((tgrp * 2 + mt) * 4 + ks) << 9) + lane * 16);
                aF[mt][ks][0] = t.x; aF[mt][ks][1] = t.y;
                aF[mt][ks][2] = t.z; aF[mt][ks][3] = t.w;
            }

        const char* pw = sm + OFF_CBP + (cgrp * 256) * 144 + g * 144 + tg * 8;
        const int row0 = tgrp * 32 + g;

        // ================= Pass 1: per-lane mins over 256 codes ============
        float mn00 = FINF, mn01 = FINF, mn10 = FINF, mn11 = FINF;
        {
            uint2 bC0 = *(const uint2*)(pw),      bC1 = *(const uint2*)(pw + 32);
            uint2 bC2 = *(const uint2*)(pw + 64), bC3 = *(const uint2*)(pw + 96);
#pragma unroll 1
            for (int j = 0; j < 32; ++j) {
                const char* pn = pw + j * 1152 + 1152;
                uint2 n0, n1, n2, n3;
                if (j < 31) {
                    n0 = *(const uint2*)(pn);      n1 = *(const uint2*)(pn + 32);
                    n2 = *(const uint2*)(pn + 64); n3 = *(const uint2*)(pn + 96);
                }
                float a0[4] = {0, 0, 0, 0}, a1[4] = {0, 0, 0, 0};
                mma16816(a0, aF[0][0], bC0.x, bC0.y); mma16816(a1, aF[1][0], bC0.x, bC0.y);
                mma16816(a0, aF[0][1], bC1.x, bC1.y); mma16816(a1, aF[1][1], bC1.x, bC1.y);
                mma16816(a0, aF[0][2], bC2.x, bC2.y); mma16816(a1, aF[1][2], bC2.x, bC2.y);
                mma16816(a0, aF[0][3], bC3.x, bC3.y); mma16816(a1, aF[1][3], bC3.x, bC3.y);
                float2 cc = s_c2p[cgrp * 128 + 4 * j + tg];
                mn00 = fminf(mn00, fminf(__fmaf_rn(-2.0f, a0[0], cc.x),
                                         __fmaf_rn(-2.0f, a0[1], cc.y)));
                mn01 = fminf(mn01, fminf(__fmaf_rn(-2.0f, a0[2], cc.x),
                                         __fmaf_rn(-2.0f, a0[3], cc.y)));
                mn10 = fminf(mn10, fminf(__fmaf_rn(-2.0f, a1[0], cc.x),
                                         __fmaf_rn(-2.0f, a1[1], cc.y)));
                mn11 = fminf(mn11, fminf(__fmaf_rn(-2.0f, a1[2], cc.x),
                                         __fmaf_rn(-2.0f, a1[3], cc.y)));
                bC0 = n0; bC1 = n1; bC2 = n2; bC3 = n3;
            }
        }
        mn00 = fminf(mn00, __shfl_xor_sync(0xFFFFFFFFu, mn00, 1));
        mn00 = fminf(mn00, __shfl_xor_sync(0xFFFFFFFFu, mn00, 2));
        mn01 = fminf(mn01, __shfl_xor_sync(0xFFFFFFFFu, mn01, 1));
        mn01 = fminf(mn01, __shfl_xor_sync(0xFFFFFFFFu, mn01, 2));
        mn10 = fminf(mn10, __shfl_xor_sync(0xFFFFFFFFu, mn10, 1));
        mn10 = fminf(mn10, __shfl_xor_sync(0xFFFFFFFFu, mn10, 2));
        mn11 = fminf(mn11, __shfl_xor_sync(0xFFFFFFFFu, mn11, 1));
        mn11 = fminf(mn11, __shfl_xor_sync(0xFFFFFFFFu, mn11, 2));
        if (tg == 0) {
            s_minw[(row0)      * 2 + cgrp] = mn00;
            s_minw[(row0 + 8)  * 2 + cgrp] = mn01;
            s_minw[(row0 + 16) * 2 + cgrp] = mn10;
            s_minw[(row0 + 24) * 2 + cgrp] = mn11;
        }
        __syncthreads();

        const float thr00 = fminf(s_minw[(row0)      * 2], s_minw[(row0)      * 2 + 1]) + WIN;
        const float thr01 = fminf(s_minw[(row0 + 8)  * 2], s_minw[(row0 + 8)  * 2 + 1]) + WIN;
        const float thr10 = fminf(s_minw[(row0 + 16) * 2], s_minw[(row0 + 16) * 2 + 1]) + WIN;
        const float thr11 = fminf(s_minw[(row0 + 24) * 2], s_minw[(row0 + 24) * 2 + 1]) + WIN;

        // ================= Pass 2: window hits -> queue ====================
        {
            uint2 bC0 = *(const uint2*)(pw),      bC1 = *(const uint2*)(pw + 32);
            uint2 bC2 = *(const uint2*)(pw + 64), bC3 = *(const uint2*)(pw + 96);
#pragma unroll 1
            for (int j = 0; j < 32; ++j) {
                const char* pn = pw + j * 1152 + 1152;
                uint2 n0, n1, n2, n3;
                if (j < 31) {
                    n0 = *(const uint2*)(pn);      n1 = *(const uint2*)(pn + 32);
                    n2 = *(const uint2*)(pn + 64); n3 = *(const uint2*)(pn + 96);
                }
                float a0[4] = {0, 0, 0, 0}, a1[4] = {0, 0, 0, 0};
                mma16816(a0, aF[0][0], bC0.x, bC0.y); mma16816(a1, aF[1][0], bC0.x, bC0.y);
                mma16816(a0, aF[0][1], bC1.x, bC1.y); mma16816(a1, aF[1][1], bC1.x, bC1.y);
                mma16816(a0, aF[0][2], bC2.x, bC2.y); mma16816(a1, aF[1][2], bC2.x, bC2.y);
                mma16816(a0, aF[0][3], bC3.x, bC3.y); mma16816(a1, aF[1][3], bC3.x, bC3.y);
                float2 cc = s_c2p[cgrp * 128 + 4 * j + tg];
                const int c0 = cgrp * 256 + 8 * j + tg * 2;
                float s0 = __fmaf_rn(-2.0f, a0[0], cc.x);
                float s1 = __fmaf_rn(-2.0f, a0[1], cc.y);
                float s2 = __fmaf_rn(-2.0f, a0[2], cc.x);
                float s3 = __fmaf_rn(-2.0f, a0[3], cc.y);
                float s4 = __fmaf_rn(-2.0f, a1[0], cc.x);
                float s5 = __fmaf_rn(-2.0f, a1[1], cc.y);
                float s6 = __fmaf_rn(-2.0f, a1[2], cc.x);
                float s7 = __fmaf_rn(-2.0f, a1[3], cc.y);
                if (s0 < thr00) { int sl = atomicAdd(s_qc, 1); if (sl < QCAP) s_q[sl] = (unsigned)((row0 << 9) | c0); }
                if (s1 < thr00) { int sl = atomicAdd(s_qc, 1); if (sl < QCAP) s_q[sl] = (unsigned)((row0 << 9) | (c0 + 1)); }
                if (s2 < thr01) { int sl = atomicAdd(s_qc, 1); if (sl < QCAP) s_q[sl] = (unsigned)(((row0 + 8) << 9) | c0); }
                if (s3 < thr01) { int sl = atomicAdd(s_qc, 1); if (sl < QCAP) s_q[sl] = (unsigned)(((row0 + 8) << 9) | (c0 + 1)); }
                if (s4 < thr10) { int sl = atomicAdd(s_qc, 1); if (sl < QCAP) s_q[sl] = (unsigned)(((row0 + 16) << 9) | c0); }
                if (s5 < thr10) { int sl = atomicAdd(s_qc, 1); if (sl < QCAP) s_q[sl] = (unsigned)(((row0 + 16) << 9) | (c0 + 1)); }
                if (s6 < thr11) { int sl = atomicAdd(s_qc, 1); if (sl < QCAP) s_q[sl] = (unsigned)(((row0 + 24) << 9) | c0); }
                if (s7 < thr11) { int sl = atomicAdd(s_qc, 1); if (sl < QCAP) s_q[sl] = (unsigned)(((row0 + 24) << 9) | (c0 + 1)); }
                bC0 = n0; bC1 = n1; bC2 = n2; bC3 = n3;
            }
        }
        __syncthreads();

        // ---- Drain queue: cooperative exact rescore ----
        {
            int nq = *s_qc;
            if (nq > QCAP) {
                if (tid < TK) {   // overflow (prob ~0): full exact scan
                    float S = s_S[tid];
                    u64 best = 0xFFFFFFFFFFFFFFFFull;
                    for (int k = 0; k < KC; ++k) {
                        const float4* rw = (const float4*)(cb + (size_t)k * DD);
                        const float4* zr = (const float4*)(z + (tok0 + tid) * DD);
                        float d = 0.0f;
#pragma unroll
                        for (int i = 0; i < DD / 4; ++i) {
                            float4 a = rw[i], b = zr[i];
                            d = __fmaf_rn(a.x, b.x, d); d = __fmaf_rn(a.y, b.y, d);
                            d = __fmaf_rn(a.z, b.z, d); d = __fmaf_rn(a.w, b.w, d);
                        }
                        float e = __fsub_rn(__fadd_rn(S, s_c2[k]), __fmul_rn(2.0f, d));
                        u64 p = ((u64)__float_as_uint(e) << 32) | (unsigned)k;
                        if (p < best) best = p;
                    }
                    atomicMin(&s_cand[tid], best);
                }
            } else {
                for (int i = tid; i < nq; i += TPB) {
                    unsigned e = s_q[i];
                    rescore(z, cb, s_c2, s_S, s_cand, tok0, (int)(e >> 9), (int)(e & 511u));
                }
            }
        }
        __syncthreads();

        // ---- Epilogue (threads 0..127): STE output + loss partial ----
        if (tid < TK) {
            int bk = (int)(s_cand[tid] & 0xFFFFFFFFull);
            const float4* q  = (const float4*)(cb + (size_t)bk * DD);
            const float4* zr = (const float4*)(z + (tok0 + tid) * DD);
            float4* op = (float4*)(out + (tok0 + tid) * DD);
            float lacc = 0.0f;
#pragma unroll
            for (int i = 0; i < DD / 4; ++i) {
                float4 cv = q[i], zv = zr[i];
                float4 o; float dx;
                dx = __fsub_rn(cv.x, zv.x); o.x = __fadd_rn(zv.x, dx); lacc = __fmaf_rn(dx, dx, lacc);
                dx = __fsub_rn(cv.y, zv.y); o.y = __fadd_rn(zv.y, dx); lacc = __fmaf_rn(dx, dx, lacc);
                dx = __fsub_rn(cv.z, zv.z); o.z = __fadd_rn(zv.z, dx); lacc = __fmaf_rn(dx, dx, lacc);
                dx = __fsub_rn(cv.w, zv.w); o.w = __fadd_rn(zv.w, dx); lacc = __fmaf_rn(dx, dx, lacc);
                op[i] = o;
            }
            my_loss += (double)lacc;
        }
        __syncthreads();
    }

    // ---- final loss reduction ----
    double dacc = my_loss;
#pragma unroll
    for (int o = 16; o > 0; o >>= 1)
        dacc += __shfl_down_sync(0xFFFFFFFFu, dacc, o);
    if (lane == 0) s_red[wid] = dacc;
    __syncthreads();
    if (tid == 0) {
        double t = 0.0;
#pragma unroll
        for (int w = 0; w < TPB / 32; ++w) t += s_red[w];
        atomicAdd(&g_loss_acc, t);
        __threadfence();
        unsigned int prev = atomicAdd(&g_done_ctr, 1u);
        if (prev == GRIDP - 1) {
            double m = atomicAdd(&g_loss_acc, 0.0) / (double)((long long)NT * DD);
            float m32 = (float)m;
            out[loss_idx] = __fadd_rn(m32, __fmul_rn(0.25f, m32));
            g_loss_acc = 0.0;
            __threadfence();
            g_done_ctr = 0u;
        }
    }
}

extern "C" void kernel_launch(void* const* d_in, const int* in_sizes, int n_in,
                              void* d_out, int out_size) {
    const float* z;
    const float* cb;
    if (in_sizes[0] == NT * DD) {
        z = (const float*)d_in[0];
        cb = (const float*)d_in[1];
    } else {
        z = (const float*)d_in[1];
        cb = (const float*)d_in[0];
    }
    float* out = (float*)d_out;

    cudaFuncSetAttribute(vq_split, cudaFuncAttributeMaxDynamicSharedMemorySize,
                         SMEM_TOTAL);
    vq_split<<<GRIDP, TPB, SMEM_TOTAL>>>(z, cb, out, out_size - 1);
}